// round 14
// baseline (speedup 1.0000x reference)
#include <cuda_runtime.h>
#include <cuda_fp16.h>
#include <cuda_bf16.h>
#include <cstdint>

#define NN 100000
#define EE 1600000
#define GG 512
#define HH 128
#define NB 98  // ceil(NN/1024)

// ---------------- scratch (device globals: no allocation allowed) ----------
__device__ __half g_bufA[NN * HH];  // GEMM output (messages y) -- fp16
__device__ float  g_bufB[NN * HH];  // SpMM output (hidden h)   -- fp32
__device__ int    g_cnt_in[NN];
__device__ int    g_cnt_out[NN];
__device__ int    g_row_ptr[NN + 1];
__device__ int    g_cursor[NN];
__device__ int2   g_epack[EE];      // per-edge {src, weight bits}, CSR-by-dst
__device__ float  g_norm_in[NN];
__device__ float  g_norm_out[NN];
__device__ float  g_graph[GG * HH]; // readout accumulator
__device__ int    g_bsum[128];

__device__ __forceinline__ uint32_t smem_u32(const void* p) {
    uint32_t a;
    asm("{ .reg .u64 t; cvta.to.shared.u64 t, %1; cvt.u32.u64 %0, t; }"
        : "=r"(a) : "l"(p));
    return a;
}

// split one fp32 pair into bf16 hi pair + bf16 lo pair (packed 32-bit each)
__device__ __forceinline__ void split2(float x, float y, uint32_t& hi, uint32_t& lo) {
    __nv_bfloat16 hx = __float2bfloat16_rn(x);
    __nv_bfloat16 hy = __float2bfloat16_rn(y);
    float rx = x - __bfloat162float(hx);
    float ry = y - __bfloat162float(hy);
    __nv_bfloat162 h2; h2.x = hx; h2.y = hy;
    __nv_bfloat162 l2 = __floats2bfloat162_rn(rx, ry);
    hi = *(uint32_t*)&h2;
    lo = *(uint32_t*)&l2;
}

// one edge, 8 features per lane: acc[0..7] += w * fp16x8(r)
__device__ __forceinline__ void fedge8(float* acc, uint4 r, float w) {
    const __half2* h = (const __half2*)&r;
#pragma unroll
    for (int q = 0; q < 4; q++) {
        float2 f = __half22float2(h[q]);
        acc[q * 2]     = fmaf(w, f.x, acc[q * 2]);
        acc[q * 2 + 1] = fmaf(w, f.y, acc[q * 2 + 1]);
    }
}

// ---------------- build kernels -------------------------------------------
__global__ void k_zero() {
    int i = blockIdx.x * blockDim.x + threadIdx.x;
    if (i < NN) { g_cnt_in[i] = 0; g_cnt_out[i] = 0; g_cursor[i] = 0; }
    if (i < GG * HH) g_graph[i] = 0.f;
}

__global__ void k_hist(const int* __restrict__ src, const int* __restrict__ dst) {
    int i = blockIdx.x * blockDim.x + threadIdx.x;
    if (i < EE) {
        atomicAdd(&g_cnt_out[src[i]], 1);
        atomicAdd(&g_cnt_in[dst[i]], 1);
    }
}

// scan1 also emits the degree norms (fused, saves one launch)
__global__ void k_scan1() {
    __shared__ int s[1024];
    int t = threadIdx.x;
    int i = blockIdx.x * 1024 + t;
    int v = (i < NN) ? g_cnt_in[i] : 0;
    if (i < NN) {
        g_norm_in[i]  = rsqrtf(fmaxf((float)v, 1.f));
        g_norm_out[i] = rsqrtf(fmaxf((float)g_cnt_out[i], 1.f));
    }
    s[t] = v;
    __syncthreads();
    for (int off = 1; off < 1024; off <<= 1) {
        int add = (t >= off) ? s[t - off] : 0;
        __syncthreads();
        s[t] += add;
        __syncthreads();
    }
    if (i < NN) g_row_ptr[i] = s[t] - v;     // block-local exclusive
    if (t == 1023) g_bsum[blockIdx.x] = s[1023];
}

// scan3 computes its own exclusive block-offset (scan2 folded in):
// each block reduces g_bsum[0..blockIdx.x) with a 128-lane shfl reduction.
__global__ void k_scan3() {
    __shared__ int warpsum[4];
    __shared__ int soff;
    int t = threadIdx.x;
    if (t < 128) {
        int v = (t < NB && t < (int)blockIdx.x) ? g_bsum[t] : 0;
#pragma unroll
        for (int o = 16; o; o >>= 1) v += __shfl_down_sync(0xffffffffu, v, o);
        if ((t & 31) == 0) warpsum[t >> 5] = v;
    }
    __syncthreads();
    if (t == 0) soff = warpsum[0] + warpsum[1] + warpsum[2] + warpsum[3];
    __syncthreads();
    int i = blockIdx.x * 1024 + t;
    if (i < NN) g_row_ptr[i] += soff;
    if (i == 0) g_row_ptr[NN] = EE;
}

__global__ void k_scatter(const int* __restrict__ src, const int* __restrict__ dst) {
    int i = blockIdx.x * blockDim.x + threadIdx.x;
    if (i < EE) {
        int d = dst[i];
        int s = src[i];
        int pos = g_row_ptr[d] + atomicAdd(&g_cursor[d], 1);
        float w = g_norm_out[s] * g_norm_in[d];
        g_epack[pos] = make_int2(s, __float_as_int(w));
    }
}

// ---------------- split-bf16 tensor-core GEMM (3-term Markidis) ------------
// C = half(A @ W) with A,W split into bf16 hi+lo; acc = hi*hi + hi*lo + lo*hi
// in fp32 -> effective fp32-grade precision on tensor cores.
// Per CTA: M=128, N=128, K=128 in four K=32 chunks. 512 threads, 16 warps 4x4,
// warp tile 32x32. A: [m][k] swizzled; W: [k][n] swizzled, ldmatrix.x2.trans.
__global__ __launch_bounds__(512) void k_gemm_mma(const float* __restrict__ A,
                                                  const float* __restrict__ W,
                                                  __half* __restrict__ C) {
    __shared__ __align__(16) unsigned char AsH[128 * 64];  // 128 r x 32 k bf16
    __shared__ __align__(16) unsigned char AsL[128 * 64];
    __shared__ __align__(16) unsigned char WsH[32 * 256];  // 32 k x 128 n bf16
    __shared__ __align__(16) unsigned char WsL[32 * 256];
    int tid = threadIdx.x;
    int wid = tid >> 5, lane = tid & 31;
    int wm = wid & 3, wn = wid >> 2;
    int row0 = blockIdx.x * 128;

    float acc[2][4][4];
#pragma unroll
    for (int mf = 0; mf < 2; mf++)
#pragma unroll
        for (int nf = 0; nf < 4; nf++)
#pragma unroll
            for (int q = 0; q < 4; q++) acc[mf][nf][q] = 0.f;

    uint32_t asH = smem_u32(AsH), asL = smem_u32(AsL);
    uint32_t wsH = smem_u32(WsH), wsL = smem_u32(WsL);

    for (int c = 0; c < 4; c++) {
        __syncthreads();
        // stage A chunk: 128 rows x 32 k; thread -> 8 floats (one 16B bf16 chunk)
        {
            int r = tid >> 2, ch = tid & 3;
            int gr = row0 + r;
            float4 f0 = make_float4(0.f, 0.f, 0.f, 0.f), f1 = f0;
            if (gr < NN) {
                const float* p = &A[gr * HH + c * 32 + ch * 8];
                f0 = *(const float4*)p;
                f1 = *(const float4*)(p + 4);
            }
            uint4 hi, lo;
            split2(f0.x, f0.y, hi.x, lo.x);
            split2(f0.z, f0.w, hi.y, lo.y);
            split2(f1.x, f1.y, hi.z, lo.z);
            split2(f1.z, f1.w, hi.w, lo.w);
            uint32_t off = r * 64 + (((uint32_t)(ch ^ ((r >> 1) & 3))) << 4);
            *(uint4*)(AsH + off) = hi;
            *(uint4*)(AsL + off) = lo;
        }
        // stage W chunk: 32 k-rows x 128 n; thread -> 8 floats
        {
            int k = tid >> 4, ch = tid & 15;
            const float* p = &W[(c * 32 + k) * HH + ch * 8];
            float4 f0 = *(const float4*)p;
            float4 f1 = *(const float4*)(p + 4);
            uint4 hi, lo;
            split2(f0.x, f0.y, hi.x, lo.x);
            split2(f0.z, f0.w, hi.y, lo.y);
            split2(f1.x, f1.y, hi.z, lo.z);
            split2(f1.z, f1.w, hi.w, lo.w);
            uint32_t off = k * 256 + (((uint32_t)(ch ^ (k & 7))) << 4);
            *(uint4*)(WsH + off) = hi;
            *(uint4*)(WsL + off) = lo;
        }
        __syncthreads();

#pragma unroll
        for (int ks = 0; ks < 2; ks++) {
            uint32_t aH[2][4], aL[2][4], bH[4][2], bL[4][2];
#pragma unroll
            for (int mf = 0; mf < 2; mf++) {
                int r = wm * 32 + mf * 16 + (lane & 15);
                int ch = ks * 2 + (lane >> 4);
                uint32_t off = r * 64 + (((uint32_t)(ch ^ ((r >> 1) & 3))) << 4);
                asm volatile(
                    "ldmatrix.sync.aligned.m8n8.x4.shared.b16 {%0,%1,%2,%3}, [%4];"
                    : "=r"(aH[mf][0]), "=r"(aH[mf][1]), "=r"(aH[mf][2]), "=r"(aH[mf][3])
                    : "r"(asH + off));
                asm volatile(
                    "ldmatrix.sync.aligned.m8n8.x4.shared.b16 {%0,%1,%2,%3}, [%4];"
                    : "=r"(aL[mf][0]), "=r"(aL[mf][1]), "=r"(aL[mf][2]), "=r"(aL[mf][3])
                    : "r"(asL + off));
            }
#pragma unroll
            for (int nf = 0; nf < 4; nf++) {
                int k = ks * 16 + (lane & 7) + ((lane >> 3) & 1) * 8;
                int ch = wn * 4 + nf;
                uint32_t off = k * 256 + (((uint32_t)(ch ^ (k & 7))) << 4);
                asm volatile(
                    "ldmatrix.sync.aligned.m8n8.x2.trans.shared.b16 {%0,%1}, [%2];"
                    : "=r"(bH[nf][0]), "=r"(bH[nf][1]) : "r"(wsH + off));
                asm volatile(
                    "ldmatrix.sync.aligned.m8n8.x2.trans.shared.b16 {%0,%1}, [%2];"
                    : "=r"(bL[nf][0]), "=r"(bL[nf][1]) : "r"(wsL + off));
            }
#define MMA_BF16(ACC, AA, BB) \
    asm volatile( \
        "mma.sync.aligned.m16n8k16.row.col.f32.bf16.bf16.f32 " \
        "{%0,%1,%2,%3}, {%4,%5,%6,%7}, {%8,%9}, {%0,%1,%2,%3};" \
        : "+f"((ACC)[0]), "+f"((ACC)[1]), "+f"((ACC)[2]), "+f"((ACC)[3]) \
        : "r"((AA)[0]), "r"((AA)[1]), "r"((AA)[2]), "r"((AA)[3]), \
          "r"((BB)[0]), "r"((BB)[1]))
#pragma unroll
            for (int mf = 0; mf < 2; mf++)
#pragma unroll
                for (int nf = 0; nf < 4; nf++) {
                    MMA_BF16(acc[mf][nf], aH[mf], bH[nf]);  // hi*hi
                    MMA_BF16(acc[mf][nf], aH[mf], bL[nf]);  // hi*lo
                    MMA_BF16(acc[mf][nf], aL[mf], bH[nf]);  // lo*hi
                }
#undef MMA_BF16
        }
    }

    // epilogue: c0,c1 -> (m = lane/4, n = (lane&3)*2, +1); c2,c3 -> m+8
#pragma unroll
    for (int mf = 0; mf < 2; mf++) {
        int gm0 = row0 + wm * 32 + mf * 16 + (lane >> 2);
#pragma unroll
        for (int nf = 0; nf < 4; nf++) {
            int gn = wn * 32 + nf * 8 + (lane & 3) * 2;
            if (gm0 < NN) {
                __half2 h = __floats2half2_rn(acc[mf][nf][0], acc[mf][nf][1]);
                *(__half2*)&C[gm0 * HH + gn] = h;
            }
            if (gm0 + 8 < NN) {
                __half2 h = __floats2half2_rn(acc[mf][nf][2], acc[mf][nf][3]);
                *(__half2*)&C[(gm0 + 8) * HH + gn] = h;
            }
        }
    }
}

// ---------------- SpMM: h[i] = relu(sum_{e:dst=i} w_e * y[src_e] + b) ------
// Warp per node; half-warp edge pairing: lanes 0-15 process even edges,
// lanes 16-31 odd edges, each lane owns 8 features (uint4 = 16B of the fp16
// row). One LDG.128 gathers TWO edge rows; one LDG.64 loads TWO edge packs.
// Arithmetic warp-instructions per edge halved vs warp-per-edge. Cross-half
// partial sums combined once at the end with 8 shfl_xor(16).
__global__ void k_spmm(const __half* __restrict__ Y, const float* __restrict__ bias,
                       float* __restrict__ Hout,
                       const int* __restrict__ n2g, int fuse) {
    int gw = (blockIdx.x * blockDim.x + threadIdx.x) >> 5;
    int lane = threadIdx.x & 31;
    int half = lane >> 4;   // even/odd edge stream
    int hl = lane & 15;     // feature group: features [hl*8, hl*8+8)
    if (gw >= NN) return;
    int beg = g_row_ptr[gw], end = g_row_ptr[gw + 1];
    const __half* Yl = Y + hl * 8;

    float acc[8];
#pragma unroll
    for (int q = 0; q < 8; q++) acc[q] = 0.f;

    int e = beg;
    // main loop: 4 pairs = 8 edges, 4 gather LDG.128 in flight
    for (; e + 8 <= end; e += 8) {
        int2 q0 = g_epack[e + 0 + half];
        int2 q1 = g_epack[e + 2 + half];
        int2 q2 = g_epack[e + 4 + half];
        int2 q3 = g_epack[e + 6 + half];
        uint4 r0 = *(const uint4*)(Yl + q0.x * HH);
        uint4 r1 = *(const uint4*)(Yl + q1.x * HH);
        uint4 r2 = *(const uint4*)(Yl + q2.x * HH);
        uint4 r3 = *(const uint4*)(Yl + q3.x * HH);
        fedge8(acc, r0, __int_as_float(q0.y));
        fedge8(acc, r1, __int_as_float(q1.y));
        fedge8(acc, r2, __int_as_float(q2.y));
        fedge8(acc, r3, __int_as_float(q3.y));
    }
    // pair remainder
    for (; e + 2 <= end; e += 2) {
        int2 q0 = g_epack[e + half];
        uint4 r0 = *(const uint4*)(Yl + q0.x * HH);
        fedge8(acc, r0, __int_as_float(q0.y));
    }
    // odd tail edge: upper half contributes zero
    if (e < end) {
        int2 q0 = g_epack[e];
        float w = half ? 0.f : __int_as_float(q0.y);
        uint4 r0 = *(const uint4*)(Yl + q0.x * HH);
        fedge8(acc, r0, w);
    }

    // combine even/odd partial sums (both halves end with the full sum)
#pragma unroll
    for (int q = 0; q < 8; q++)
        acc[q] += __shfl_xor_sync(0xffffffffu, acc[q], 16);

    const float4* bp = (const float4*)&bias[hl * 8];
    float4 b0 = bp[0], b1 = bp[1];
    float h[8];
    h[0] = fmaxf(acc[0] + b0.x, 0.f); h[1] = fmaxf(acc[1] + b0.y, 0.f);
    h[2] = fmaxf(acc[2] + b0.z, 0.f); h[3] = fmaxf(acc[3] + b0.w, 0.f);
    h[4] = fmaxf(acc[4] + b1.x, 0.f); h[5] = fmaxf(acc[5] + b1.y, 0.f);
    h[6] = fmaxf(acc[6] + b1.z, 0.f); h[7] = fmaxf(acc[7] + b1.w, 0.f);

    if (!fuse) {
        // half 0 writes features [8hl,8hl+4), half 1 writes [8hl+4,8hl+8)
        float4 o = half ? make_float4(h[4], h[5], h[6], h[7])
                        : make_float4(h[0], h[1], h[2], h[3]);
        *(float4*)&Hout[gw * HH + hl * 8 + half * 4] = o;
    } else {
        int gi = n2g[gw];
        float* p = &g_graph[gi * HH + hl * 8 + half * 4];
        const float* hp = h + half * 4;
#pragma unroll
        for (int q = 0; q < 4; q++) atomicAdd(p + q, hp[q]);
    }
}

// ---------------- MLP head: out[g] = relu(g_row @ Wm1 + bm1) @ Wm2 + bm2 ---
__global__ __launch_bounds__(128) void k_mlp(const float* __restrict__ Wm1,
                                             const float* __restrict__ bm1,
                                             const float* __restrict__ Wm2,
                                             const float* __restrict__ bm2,
                                             float* __restrict__ out) {
    __shared__ float gv[HH];
    __shared__ float red[4];
    int t = threadIdx.x, gi = blockIdx.x;
    gv[t] = g_graph[gi * HH + t];
    __syncthreads();
    float s = bm1[t];
#pragma unroll 8
    for (int k = 0; k < HH; k++) s = fmaf(gv[k], Wm1[k * HH + t], s);
    float p = fmaxf(s, 0.f) * Wm2[t];
#pragma unroll
    for (int off = 16; off; off >>= 1) p += __shfl_down_sync(0xffffffffu, p, off);
    if ((t & 31) == 0) red[t >> 5] = p;
    __syncthreads();
    if (t == 0) out[gi] = red[0] + red[1] + red[2] + red[3] + bm2[0];
}

// ---------------- launcher --------------------------------------------------
extern "C" void kernel_launch(void* const* d_in, const int* in_sizes, int n_in,
                              void* d_out, int out_size) {
    const float* x   = (const float*)d_in[0];
    const int*   src = (const int*)d_in[1];
    const int*   dst = (const int*)d_in[2];
    const int*   n2g = (const int*)d_in[3];
    const float* W0  = (const float*)d_in[4];
    const float* b0  = (const float*)d_in[5];
    const float* W1  = (const float*)d_in[6];
    const float* b1  = (const float*)d_in[7];
    const float* W2  = (const float*)d_in[8];
    const float* b2  = (const float*)d_in[9];
    const float* Wm1 = (const float*)d_in[10];
    const float* bm1 = (const float*)d_in[11];
    const float* Wm2 = (const float*)d_in[12];
    const float* bm2 = (const float*)d_in[13];
    float* out = (float*)d_out;

    __half* bufA;
    float*  bufB;
    cudaGetSymbolAddress((void**)&bufA, g_bufA);
    cudaGetSymbolAddress((void**)&bufB, g_bufB);

    const int TB = 256;
    // graph structure build (rebuilt each launch: determinism rules)
    k_zero<<<(NN + TB - 1) / TB, TB>>>();
    k_hist<<<(EE + TB - 1) / TB, TB>>>(src, dst);
    k_scan1<<<NB, 1024>>>();
    k_scan3<<<NB, 1024>>>();
    k_scatter<<<(EE + TB - 1) / TB, TB>>>(src, dst);

    const int gemmGrid = (NN + 127) / 128;          // 782
    const int spmmGrid = (NN * 32 + TB - 1) / TB;   // warp per node

    // layer 0
    k_gemm_mma<<<gemmGrid, 512>>>(x, W0, bufA);
    k_spmm<<<spmmGrid, TB>>>(bufA, b0, bufB, n2g, 0);
    // layer 1
    k_gemm_mma<<<gemmGrid, 512>>>(bufB, W1, bufA);
    k_spmm<<<spmmGrid, TB>>>(bufA, b1, bufB, n2g, 0);
    // layer 2 (readout fused into SpMM epilogue)
    k_gemm_mma<<<gemmGrid, 512>>>(bufB, W2, bufA);
    k_spmm<<<spmmGrid, TB>>>(bufA, b2, bufB, n2g, 1);
    // head
    k_mlp<<<GG, 128>>>(Wm1, bm1, Wm2, bm2, out);
}

// round 15
// speedup vs baseline: 1.4957x; 1.4957x over previous
#include <cuda_runtime.h>
#include <cuda_fp16.h>
#include <cuda_bf16.h>
#include <cstdint>

#define NN 100000
#define EE 1600000
#define GG 512
#define HH 128
#define NB 98  // ceil(NN/1024)

// ---------------- scratch (device globals: no allocation allowed) ----------
__device__ __half g_bufA[NN * HH];  // GEMM output (messages y) -- fp16
__device__ float  g_bufB[NN * HH];  // SpMM output (hidden h)   -- fp32
__device__ int    g_cnt_in[NN];
__device__ int    g_cnt_out[NN];
__device__ int    g_row_ptr[NN + 1];
__device__ int    g_cursor[NN];
__device__ int2   g_epack[EE];      // per-edge {src, weight bits}, CSR-by-dst
__device__ float  g_norm_in[NN];
__device__ float  g_norm_out[NN];
__device__ float  g_graph[GG * HH]; // readout accumulator
__device__ int    g_bsum[128];

__device__ __forceinline__ uint32_t smem_u32(const void* p) {
    uint32_t a;
    asm("{ .reg .u64 t; cvta.to.shared.u64 t, %1; cvt.u32.u64 %0, t; }"
        : "=r"(a) : "l"(p));
    return a;
}

// split one fp32 pair into bf16 hi pair + bf16 lo pair (packed 32-bit each)
__device__ __forceinline__ void split2(float x, float y, uint32_t& hi, uint32_t& lo) {
    __nv_bfloat16 hx = __float2bfloat16_rn(x);
    __nv_bfloat16 hy = __float2bfloat16_rn(y);
    float rx = x - __bfloat162float(hx);
    float ry = y - __bfloat162float(hy);
    __nv_bfloat162 h2; h2.x = hx; h2.y = hy;
    __nv_bfloat162 l2 = __floats2bfloat162_rn(rx, ry);
    hi = *(uint32_t*)&h2;
    lo = *(uint32_t*)&l2;
}

// one edge: acc += w * fp16row(8B per lane as 2x half2)  [R9 structure]
__device__ __forceinline__ void fedge(float4& acc, uint2 r, float w) {
    float2 a = __half22float2(*(__half2*)&r.x);
    float2 b = __half22float2(*(__half2*)&r.y);
    acc.x = fmaf(w, a.x, acc.x);
    acc.y = fmaf(w, a.y, acc.y);
    acc.z = fmaf(w, b.x, acc.z);
    acc.w = fmaf(w, b.y, acc.w);
}

// ---------------- build kernels -------------------------------------------
__global__ void k_zero() {
    int i = blockIdx.x * blockDim.x + threadIdx.x;
    if (i < NN) { g_cnt_in[i] = 0; g_cnt_out[i] = 0; g_cursor[i] = 0; }
    if (i < GG * HH) g_graph[i] = 0.f;
}

__global__ void k_hist(const int* __restrict__ src, const int* __restrict__ dst) {
    int i = blockIdx.x * blockDim.x + threadIdx.x;
    if (i < EE) {
        atomicAdd(&g_cnt_out[src[i]], 1);
        atomicAdd(&g_cnt_in[dst[i]], 1);
    }
}

// scan1 also emits the degree norms (fused, saves one launch)
__global__ void k_scan1() {
    __shared__ int s[1024];
    int t = threadIdx.x;
    int i = blockIdx.x * 1024 + t;
    int v = (i < NN) ? g_cnt_in[i] : 0;
    if (i < NN) {
        g_norm_in[i]  = rsqrtf(fmaxf((float)v, 1.f));
        g_norm_out[i] = rsqrtf(fmaxf((float)g_cnt_out[i], 1.f));
    }
    s[t] = v;
    __syncthreads();
    for (int off = 1; off < 1024; off <<= 1) {
        int add = (t >= off) ? s[t - off] : 0;
        __syncthreads();
        s[t] += add;
        __syncthreads();
    }
    if (i < NN) g_row_ptr[i] = s[t] - v;     // block-local exclusive
    if (t == 1023) g_bsum[blockIdx.x] = s[1023];
}

// scan3 computes its own exclusive block-offset (scan2 folded in):
// each block reduces g_bsum[0..blockIdx.x) with a 128-lane shfl reduction.
__global__ void k_scan3() {
    __shared__ int warpsum[4];
    __shared__ int soff;
    int t = threadIdx.x;
    if (t < 128) {
        int v = (t < NB && t < (int)blockIdx.x) ? g_bsum[t] : 0;
#pragma unroll
        for (int o = 16; o; o >>= 1) v += __shfl_down_sync(0xffffffffu, v, o);
        if ((t & 31) == 0) warpsum[t >> 5] = v;
    }
    __syncthreads();
    if (t == 0) soff = warpsum[0] + warpsum[1] + warpsum[2] + warpsum[3];
    __syncthreads();
    int i = blockIdx.x * 1024 + t;
    if (i < NN) g_row_ptr[i] += soff;
    if (i == 0) g_row_ptr[NN] = EE;
}

__global__ void k_scatter(const int* __restrict__ src, const int* __restrict__ dst) {
    int i = blockIdx.x * blockDim.x + threadIdx.x;
    if (i < EE) {
        int d = dst[i];
        int s = src[i];
        int pos = g_row_ptr[d] + atomicAdd(&g_cursor[d], 1);
        float w = g_norm_out[s] * g_norm_in[d];
        g_epack[pos] = make_int2(s, __float_as_int(w));
    }
}

// ---------------- split-bf16 tensor-core GEMM (3-term Markidis) ------------
// C = half(A @ W) with A,W split into bf16 hi+lo; acc = hi*hi + hi*lo + lo*hi
// in fp32 -> effective fp32-grade precision on tensor cores.
// Per CTA: M=128, N=128, K=128 in four K=32 chunks. 512 threads, 16 warps 4x4,
// warp tile 32x32. A: [m][k] swizzled; W: [k][n] swizzled, ldmatrix.x2.trans.
__global__ __launch_bounds__(512) void k_gemm_mma(const float* __restrict__ A,
                                                  const float* __restrict__ W,
                                                  __half* __restrict__ C) {
    __shared__ __align__(16) unsigned char AsH[128 * 64];  // 128 r x 32 k bf16
    __shared__ __align__(16) unsigned char AsL[128 * 64];
    __shared__ __align__(16) unsigned char WsH[32 * 256];  // 32 k x 128 n bf16
    __shared__ __align__(16) unsigned char WsL[32 * 256];
    int tid = threadIdx.x;
    int wid = tid >> 5, lane = tid & 31;
    int wm = wid & 3, wn = wid >> 2;
    int row0 = blockIdx.x * 128;

    float acc[2][4][4];
#pragma unroll
    for (int mf = 0; mf < 2; mf++)
#pragma unroll
        for (int nf = 0; nf < 4; nf++)
#pragma unroll
            for (int q = 0; q < 4; q++) acc[mf][nf][q] = 0.f;

    uint32_t asH = smem_u32(AsH), asL = smem_u32(AsL);
    uint32_t wsH = smem_u32(WsH), wsL = smem_u32(WsL);

    for (int c = 0; c < 4; c++) {
        __syncthreads();
        // stage A chunk: 128 rows x 32 k; thread -> 8 floats (one 16B bf16 chunk)
        {
            int r = tid >> 2, ch = tid & 3;
            int gr = row0 + r;
            float4 f0 = make_float4(0.f, 0.f, 0.f, 0.f), f1 = f0;
            if (gr < NN) {
                const float* p = &A[gr * HH + c * 32 + ch * 8];
                f0 = *(const float4*)p;
                f1 = *(const float4*)(p + 4);
            }
            uint4 hi, lo;
            split2(f0.x, f0.y, hi.x, lo.x);
            split2(f0.z, f0.w, hi.y, lo.y);
            split2(f1.x, f1.y, hi.z, lo.z);
            split2(f1.z, f1.w, hi.w, lo.w);
            uint32_t off = r * 64 + (((uint32_t)(ch ^ ((r >> 1) & 3))) << 4);
            *(uint4*)(AsH + off) = hi;
            *(uint4*)(AsL + off) = lo;
        }
        // stage W chunk: 32 k-rows x 128 n; thread -> 8 floats
        {
            int k = tid >> 4, ch = tid & 15;
            const float* p = &W[(c * 32 + k) * HH + ch * 8];
            float4 f0 = *(const float4*)p;
            float4 f1 = *(const float4*)(p + 4);
            uint4 hi, lo;
            split2(f0.x, f0.y, hi.x, lo.x);
            split2(f0.z, f0.w, hi.y, lo.y);
            split2(f1.x, f1.y, hi.z, lo.z);
            split2(f1.z, f1.w, hi.w, lo.w);
            uint32_t off = k * 256 + (((uint32_t)(ch ^ (k & 7))) << 4);
            *(uint4*)(WsH + off) = hi;
            *(uint4*)(WsL + off) = lo;
        }
        __syncthreads();

#pragma unroll
        for (int ks = 0; ks < 2; ks++) {
            uint32_t aH[2][4], aL[2][4], bH[4][2], bL[4][2];
#pragma unroll
            for (int mf = 0; mf < 2; mf++) {
                int r = wm * 32 + mf * 16 + (lane & 15);
                int ch = ks * 2 + (lane >> 4);
                uint32_t off = r * 64 + (((uint32_t)(ch ^ ((r >> 1) & 3))) << 4);
                asm volatile(
                    "ldmatrix.sync.aligned.m8n8.x4.shared.b16 {%0,%1,%2,%3}, [%4];"
                    : "=r"(aH[mf][0]), "=r"(aH[mf][1]), "=r"(aH[mf][2]), "=r"(aH[mf][3])
                    : "r"(asH + off));
                asm volatile(
                    "ldmatrix.sync.aligned.m8n8.x4.shared.b16 {%0,%1,%2,%3}, [%4];"
                    : "=r"(aL[mf][0]), "=r"(aL[mf][1]), "=r"(aL[mf][2]), "=r"(aL[mf][3])
                    : "r"(asL + off));
            }
#pragma unroll
            for (int nf = 0; nf < 4; nf++) {
                int k = ks * 16 + (lane & 7) + ((lane >> 3) & 1) * 8;
                int ch = wn * 4 + nf;
                uint32_t off = k * 256 + (((uint32_t)(ch ^ (k & 7))) << 4);
                asm volatile(
                    "ldmatrix.sync.aligned.m8n8.x2.trans.shared.b16 {%0,%1}, [%2];"
                    : "=r"(bH[nf][0]), "=r"(bH[nf][1]) : "r"(wsH + off));
                asm volatile(
                    "ldmatrix.sync.aligned.m8n8.x2.trans.shared.b16 {%0,%1}, [%2];"
                    : "=r"(bL[nf][0]), "=r"(bL[nf][1]) : "r"(wsL + off));
            }
#define MMA_BF16(ACC, AA, BB) \
    asm volatile( \
        "mma.sync.aligned.m16n8k16.row.col.f32.bf16.bf16.f32 " \
        "{%0,%1,%2,%3}, {%4,%5,%6,%7}, {%8,%9}, {%0,%1,%2,%3};" \
        : "+f"((ACC)[0]), "+f"((ACC)[1]), "+f"((ACC)[2]), "+f"((ACC)[3]) \
        : "r"((AA)[0]), "r"((AA)[1]), "r"((AA)[2]), "r"((AA)[3]), \
          "r"((BB)[0]), "r"((BB)[1]))
#pragma unroll
            for (int mf = 0; mf < 2; mf++)
#pragma unroll
                for (int nf = 0; nf < 4; nf++) {
                    MMA_BF16(acc[mf][nf], aH[mf], bH[nf]);  // hi*hi
                    MMA_BF16(acc[mf][nf], aH[mf], bL[nf]);  // hi*lo
                    MMA_BF16(acc[mf][nf], aL[mf], bH[nf]);  // lo*hi
                }
#undef MMA_BF16
        }
    }

    // epilogue: c0,c1 -> (m = lane/4, n = (lane&3)*2, +1); c2,c3 -> m+8
#pragma unroll
    for (int mf = 0; mf < 2; mf++) {
        int gm0 = row0 + wm * 32 + mf * 16 + (lane >> 2);
#pragma unroll
        for (int nf = 0; nf < 4; nf++) {
            int gn = wn * 32 + nf * 8 + (lane & 3) * 2;
            if (gm0 < NN) {
                __half2 h = __floats2half2_rn(acc[mf][nf][0], acc[mf][nf][1]);
                *(__half2*)&C[gm0 * HH + gn] = h;
            }
            if (gm0 + 8 < NN) {
                __half2 h = __floats2half2_rn(acc[mf][nf][2], acc[mf][nf][3]);
                *(__half2*)&C[(gm0 + 8) * HH + gn] = h;
            }
        }
    }
}

// ---------------- SpMM: h[i] = relu(sum_{e:dst=i} w_e * y[src_e] + b) ------
// R9 structure (measured best): one warp per destination node, lane owns 4
// contiguous fp16 features (uint2 = 8B/lane -> one 256B row per gather LDG),
// 4 independent gathers in flight. Only delta vs R9: packed int2 edge loads
// (one uniform LDG.64 per edge instead of two scalar LDGs).
__global__ void k_spmm(const __half* __restrict__ Y, const float* __restrict__ bias,
                       float* __restrict__ Hout,
                       const int* __restrict__ n2g, int fuse) {
    int gw = (blockIdx.x * blockDim.x + threadIdx.x) >> 5;
    int lane = threadIdx.x & 31;
    if (gw >= NN) return;
    int beg = g_row_ptr[gw], end = g_row_ptr[gw + 1];
    const __half* Yl = Y + lane * 4;

    float4 acc = make_float4(0.f, 0.f, 0.f, 0.f);
    int e = beg;
    for (; e + 4 <= end; e += 4) {
        int2 p0 = g_epack[e + 0], p1 = g_epack[e + 1];
        int2 p2 = g_epack[e + 2], p3 = g_epack[e + 3];
        uint2 r0 = *(const uint2*)(Yl + p0.x * HH);
        uint2 r1 = *(const uint2*)(Yl + p1.x * HH);
        uint2 r2 = *(const uint2*)(Yl + p2.x * HH);
        uint2 r3 = *(const uint2*)(Yl + p3.x * HH);
        fedge(acc, r0, __int_as_float(p0.y));
        fedge(acc, r1, __int_as_float(p1.y));
        fedge(acc, r2, __int_as_float(p2.y));
        fedge(acc, r3, __int_as_float(p3.y));
    }
    for (; e < end; e++) {
        int2 p0 = g_epack[e];
        uint2 r0 = *(const uint2*)(Yl + p0.x * HH);
        fedge(acc, r0, __int_as_float(p0.y));
    }

    float4 b = *(const float4*)&bias[lane * 4];
    float4 h;
    h.x = fmaxf(acc.x + b.x, 0.f);
    h.y = fmaxf(acc.y + b.y, 0.f);
    h.z = fmaxf(acc.z + b.z, 0.f);
    h.w = fmaxf(acc.w + b.w, 0.f);

    if (!fuse) {
        *(float4*)&Hout[gw * HH + lane * 4] = h;
    } else {
        int gi = n2g[gw];
        float* p = &g_graph[gi * HH + lane * 4];
        atomicAdd(p + 0, h.x); atomicAdd(p + 1, h.y);
        atomicAdd(p + 2, h.z); atomicAdd(p + 3, h.w);
    }
}

// ---------------- MLP head: out[g] = relu(g_row @ Wm1 + bm1) @ Wm2 + bm2 ---
__global__ __launch_bounds__(128) void k_mlp(const float* __restrict__ Wm1,
                                             const float* __restrict__ bm1,
                                             const float* __restrict__ Wm2,
                                             const float* __restrict__ bm2,
                                             float* __restrict__ out) {
    __shared__ float gv[HH];
    __shared__ float red[4];
    int t = threadIdx.x, gi = blockIdx.x;
    gv[t] = g_graph[gi * HH + t];
    __syncthreads();
    float s = bm1[t];
#pragma unroll 8
    for (int k = 0; k < HH; k++) s = fmaf(gv[k], Wm1[k * HH + t], s);
    float p = fmaxf(s, 0.f) * Wm2[t];
#pragma unroll
    for (int off = 16; off; off >>= 1) p += __shfl_down_sync(0xffffffffu, p, off);
    if ((t & 31) == 0) red[t >> 5] = p;
    __syncthreads();
    if (t == 0) out[gi] = red[0] + red[1] + red[2] + red[3] + bm2[0];
}

// ---------------- launcher --------------------------------------------------
extern "C" void kernel_launch(void* const* d_in, const int* in_sizes, int n_in,
                              void* d_out, int out_size) {
    const float* x   = (const float*)d_in[0];
    const int*   src = (const int*)d_in[1];
    const int*   dst = (const int*)d_in[2];
    const int*   n2g = (const int*)d_in[3];
    const float* W0  = (const float*)d_in[4];
    const float* b0  = (const float*)d_in[5];
    const float* W1  = (const float*)d_in[6];
    const float* b1  = (const float*)d_in[7];
    const float* W2  = (const float*)d_in[8];
    const float* b2  = (const float*)d_in[9];
    const float* Wm1 = (const float*)d_in[10];
    const float* bm1 = (const float*)d_in[11];
    const float* Wm2 = (const float*)d_in[12];
    const float* bm2 = (const float*)d_in[13];
    float* out = (float*)d_out;

    __half* bufA;
    float*  bufB;
    cudaGetSymbolAddress((void**)&bufA, g_bufA);
    cudaGetSymbolAddress((void**)&bufB, g_bufB);

    const int TB = 256;
    const int gemmGrid = (NN + 127) / 128;          // 782
    const int spmmGrid = (NN * 32 + TB - 1) / TB;   // warp per node

    // graph structure build (rebuilt each launch: determinism rules).
    // GEMM-0 depends only on x/W0, so it is hoisted into launch slot 4 —
    // the slot the ncu capture window lands on — to get a real GEMM profile.
    k_zero<<<(NN + TB - 1) / TB, TB>>>();           // 1
    k_hist<<<(EE + TB - 1) / TB, TB>>>(src, dst);   // 2
    k_scan1<<<NB, 1024>>>();                        // 3
    k_gemm_mma<<<gemmGrid, 512>>>(x, W0, bufA);     // 4  <- profiled launch
    k_scan3<<<NB, 1024>>>();                        // 5
    k_scatter<<<(EE + TB - 1) / TB, TB>>>(src, dst);// 6

    // layer 0 aggregation
    k_spmm<<<spmmGrid, TB>>>(bufA, b0, bufB, n2g, 0);
    // layer 1
    k_gemm_mma<<<gemmGrid, 512>>>(bufB, W1, bufA);
    k_spmm<<<spmmGrid, TB>>>(bufA, b1, bufB, n2g, 0);
    // layer 2 (readout fused into SpMM epilogue)
    k_gemm_mma<<<gemmGrid, 512>>>(bufB, W2, bufA);
    k_spmm<<<spmmGrid, TB>>>(bufA, b2, bufB, n2g, 1);
    // head
    k_mlp<<<GG, 128>>>(Wm1, bm1, Wm2, bm2, out);
}